// round 9
// baseline (speedup 1.0000x reference)
#include <cuda_runtime.h>
#include <cstdint>

// Shapes (fixed by the problem)
#define N_SAMP 32768
#define D_DIM  256
#define M_ST   4
#define K_CODE 1024

// Output layout (element offsets into f32 d_out)
#define OFF_XQ   0
#define OFF_LOSS 8388608
#define OFF_IDX  8388609
#define OFF_EMB  8519681
#define OFF_AVG  9568257
#define OFF_CS   10616833
#define OUT_TOT  10620929

// Scratch (device globals — no allocation allowed)
__device__ __align__(16) float g_part[256 * 256];   // per-block column partials of x
__device__ __align__(16) float g_invw[4 * 1024];    // 1/weights per (stage, code)

// ---------------------------------------------------------------------------
// K1: read-heavy + write-heavy work co-scheduled in one grid (blockDim=256):
//   [0,256)      colsum partials of x (float4)  -> g_part   (read stream)
//   [256,260)    cluster_size outputs + invw    -> g_invw
//   [260,2340)   x_q + zero region writer (4 float4 stores/thread)
// ---------------------------------------------------------------------------
__global__ void __launch_bounds__(256) k1_fused(
        const float* __restrict__ x,
        const float* __restrict__ emb,
        const float* __restrict__ cs_in,
        float* __restrict__ out, int out_size) {
    const int b = blockIdx.x;
    const int tid = threadIdx.x;

    if (b < 256) {
        // ---- colsum partial: block b covers rows [b*128, b*128+128)
        const int r_off = tid >> 6;
        const int c4 = tid & 63;
        const float4* x4 = (const float4*)x;
        float4 acc = make_float4(0.f, 0.f, 0.f, 0.f);
        const long base = (long)b * 128 * 64 + c4;
#pragma unroll 8
        for (int r = r_off; r < 128; r += 4) {
            float4 v = x4[base + (long)r * 64];
            acc.x += v.x; acc.y += v.y; acc.z += v.z; acc.w += v.w;
        }
        __shared__ float4 s4[256];
        s4[tid] = acc;
        __syncthreads();
        if (tid < 64) {
            float4 a = s4[tid], b1 = s4[tid + 64], c = s4[tid + 128], d = s4[tid + 192];
            float4 r;
            r.x = ((a.x + b1.x) + c.x) + d.x;
            r.y = ((a.y + b1.y) + c.y) + d.y;
            r.z = ((a.z + b1.z) + c.z) + d.z;
            r.w = ((a.w + b1.w) + c.w) + d.w;
            ((float4*)g_part)[b * 64 + tid] = r;
        }
    } else if (b < 260) {
        // ---- invw + cluster_size outputs for stage i
        const int i = b - 256;
        __shared__ float red[256];
        const float* csr = cs_in + i * K_CODE;
        {
            float s = ((csr[tid] + csr[tid + 256]) + csr[tid + 512]) + csr[tid + 768];
            red[tid] = s;
            __syncthreads();
            for (int st = 128; st > 0; st >>= 1) {
                if (tid < st) red[tid] += red[tid + st];
                __syncthreads();
            }
        }
        const float n = 0.99f * red[0] + 327.68f;
        const float denom = n + 1024.0f * 1e-5f;
#pragma unroll
        for (int j = 0; j < 4; ++j) {
            const int k = tid + j * 256;
            const float c = csr[k] * 0.99f + ((k == 0) ? 327.68f : 0.f);
            const int o = OFF_CS + i * K_CODE + k;
            if (o < out_size) out[o] = c;
            const float w = (c + 1e-5f) / denom * n;
            g_invw[i * K_CODE + k] = 1.0f / w;
        }
    } else {
        // ---- x_q + zero region writer. v in [0, 532480); 4 stores at stride
        // 532480 float4. 532480 % 64 == 0 so the pattern column is invariant.
        const int v = (b - 260) * 256 + tid;
        const int c4 = v & 63;
        const float4* e4p = (const float4*)emb;
        float4 s0 = e4p[0 * 65536 + c4];
        float4 s1 = e4p[1 * 65536 + c4];
        float4 s2 = e4p[2 * 65536 + c4];
        float4 s3 = e4p[3 * 65536 + c4];
        float4 s;
        s.x = ((s0.x + s1.x) + s2.x) + s3.x;
        s.y = ((s0.y + s1.y) + s2.y) + s3.y;
        s.z = ((s0.z + s1.z) + s2.z) + s3.z;
        s.w = ((s0.w + s1.w) + s2.w) + s3.w;
        const float4 z = make_float4(0.f, 0.f, 0.f, 0.f);
        float4* o4 = (float4*)out;
#pragma unroll
        for (int j = 0; j < 4; ++j) {
            const long e4 = (long)v + (long)j * 532480;  // < 2129920
            if (e4 * 4 + 3 < out_size)
                o4[e4] = (e4 < 2097152) ? s : z;
        }
        if (v == 0 && 8519680 < out_size) out[8519680] = 0.f;  // tail scalar
    }
}

// ---------------------------------------------------------------------------
// K2: emb/avg outputs. blocks [0,4) = row0 (reads g_part), [4,260) = stream.
// Ordered after K1 by the kernel boundary — no fences or spins needed.
// ---------------------------------------------------------------------------
__global__ void __launch_bounds__(256) k2_emb_avg(
        const float* __restrict__ emb,
        const float* __restrict__ avg,
        float* __restrict__ out, int out_size) {
    const int b = blockIdx.x;
    const int tid = threadIdx.x;

    if (b < 4) {
        // ---- k==0 row of stage i; d = tid
        const int i = b;
        const int d = tid;
        float sx = 0.f;
#pragma unroll 16
        for (int p = 0; p < 256; ++p)
            sx += g_part[p * D_DIM + d];
        float pi = 0.f;
        for (int j = 0; j < i; ++j) pi += emb[(size_t)j * K_CODE * D_DIM + d];
        const float sum_term = sx - 32768.0f * pi;
        const int t = i * K_CODE * D_DIM + d;            // (i, 0, d)
        const float na = 0.99f * avg[t] + 0.01f * sum_term;
        const float iw = g_invw[i * K_CODE];             // k == 0
        const int oa = OFF_AVG + t;
        const int oe = OFF_EMB + t;
        if (oa < out_size) out[oa] = na;
        if (oe < out_size) out[oe] = na * iw;
    } else {
        // ---- stream: block covers 4096 consecutive elements, no barriers
        const int blk = b - 4;                           // [0, 256)
#pragma unroll
        for (int j = 0; j < 16; ++j) {
            const int t = blk * 4096 + j * 256 + tid;
            const int row = t >> 8;
            if ((row & (K_CODE - 1)) == 0) continue;     // row0 handled above
            const float na = 0.99f * avg[t];             // sum_term == 0 for k != 0
            const float iw = g_invw[row];
            const int oa = OFF_AVG + t;
            const int oe = OFF_EMB + t;
            if (oa < out_size) out[oa] = na;
            if (oe < out_size) out[oe] = na * iw;
        }
    }
}

extern "C" void kernel_launch(void* const* d_in, const int* in_sizes, int n_in,
                              void* d_out, int out_size) {
    const float* x   = (const float*)d_in[0];  // [N, D]
    const float* emb = (const float*)d_in[1];  // [M, K, D]
    const float* avg = (const float*)d_in[2];  // [M, K, D]
    const float* cs  = (const float*)d_in[3];  // [M, K]
    float* out = (float*)d_out;

    k1_fused<<<2340, 256>>>(x, emb, cs, out, out_size);
    k2_emb_avg<<<260, 256>>>(emb, avg, out, out_size);
}